// round 16
// baseline (speedup 1.0000x reference)
#include <cuda_runtime.h>
#include <cuda_fp16.h>
#include <math.h>
#include <stdint.h>

// ---------------- static scratch (no runtime allocation allowed) ----------------
#define MAXN 50000
#define NPADMAX (3 * 50048)          // per-type padded to 128 rows
#define MAXET (3 * 400000)

__device__ float g_hl[NPADMAX * 256];
__device__ float g_hr[NPADMAX * 256];
__device__ float g_h [NPADMAX * 256];
__device__ float g_hn[NPADMAX * 256];
__device__ __half g_Ah[NPADMAX * 256];
__device__ __half g_Bh[3 * (128 + 256) * 512];
__device__ int   g_rowptr[NPADMAX + 1];
__device__ int   g_csrsrc[MAXET];
__device__ int   g_deg[NPADMAX];
__device__ int   g_cursor[NPADMAX];
__device__ int   g_bsum[256];
__device__ float g_bnsum[768];
__device__ float g_bnsq[768];
__device__ float g_scale[768];
__device__ float g_shift[768];

#define L2_WOFF (3 * 128 * 512)      // offset of layer-2 weights inside g_Bh

// ---------------- baseline-PTX helpers (no 'a'-suffix features) ----------------
__device__ __forceinline__ uint32_t smem_u32(const void* p) {
    uint32_t a;
    asm("{ .reg .u64 t; cvta.to.shared.u64 t, %1; cvt.u32.u64 %0, t; }" : "=r"(a) : "l"(p));
    return a;
}
__device__ __forceinline__ void cp_async16(uint32_t dst, const void* src) {
    asm volatile("cp.async.cg.shared.global [%0], [%1], 16;" :: "r"(dst), "l"(src));
}
__device__ __forceinline__ void cp_commit() { asm volatile("cp.async.commit_group;" ::: "memory"); }
template <int N>
__device__ __forceinline__ void cp_wait() { asm volatile("cp.async.wait_group %0;" :: "n"(N) : "memory"); }

__device__ __forceinline__ void ldmat_x4(uint32_t addr, uint32_t& r0, uint32_t& r1,
                                         uint32_t& r2, uint32_t& r3) {
    asm volatile("ldmatrix.sync.aligned.m8n8.x4.shared.b16 {%0,%1,%2,%3}, [%4];"
                 : "=r"(r0), "=r"(r1), "=r"(r2), "=r"(r3) : "r"(addr));
}
__device__ __forceinline__ void ldmat_x4_t(uint32_t addr, uint32_t& r0, uint32_t& r1,
                                           uint32_t& r2, uint32_t& r3) {
    asm volatile("ldmatrix.sync.aligned.m8n8.x4.trans.shared.b16 {%0,%1,%2,%3}, [%4];"
                 : "=r"(r0), "=r"(r1), "=r"(r2), "=r"(r3) : "r"(addr));
}
__device__ __forceinline__ void mma_f16(float& c0, float& c1, float& c2, float& c3,
                                        uint32_t a0, uint32_t a1, uint32_t a2, uint32_t a3,
                                        uint32_t b0, uint32_t b1) {
    asm volatile("mma.sync.aligned.m16n8k16.row.col.f32.f16.f16.f32 "
                 "{%0,%1,%2,%3}, {%4,%5,%6,%7}, {%8,%9}, {%0,%1,%2,%3};"
                 : "+f"(c0), "+f"(c1), "+f"(c2), "+f"(c3)
                 : "r"(a0), "r"(a1), "r"(a2), "r"(a3), "r"(b0), "r"(b1));
}

// ---------------- HMMA GEMM: [hl|hr][M,256] = A[Mpad,K] @ Bcat_type[K,512] ----------------
// Single-fp16 A and B. 3-stage cp.async pipeline, one __syncthreads per chunk.
// SMEM per stage: Ah[128][40]h @0, Bh[32][136]h @10240
#define KC 32
#define A_STR 40
#define B_STR 136
#define S_AH 0
#define S_BH 10240
#define STAGE_B 18944
#define GEMM_SMEM (3 * STAGE_B)

__global__ __launch_bounds__(256) void gemm_mma_kernel(
    const __half* __restrict__ Ah, const __half* __restrict__ BhAll,
    float* __restrict__ Cl, float* __restrict__ Cr,
    int P1, int P2, int N0, int N1, int N2, int K, int wbase)
{
    extern __shared__ char smem[];
    const uint32_t sb = smem_u32(smem);
    const int tid  = threadIdx.x;
    const int lane = tid & 31;
    const int w    = tid >> 5;
    const int wm   = (w & 3) * 32;
    const int wn   = (w >> 2) * 64;
    const int bm   = blockIdx.y * 128;
    const int bn   = blockIdx.x * 128;   // within 512 concat cols

    const int t  = (bm >= P2) ? 2 : (bm >= P1 ? 1 : 0);
    const int Pt = (t == 2) ? P2 : (t == 1 ? P1 : 0);
    const int Nt = (t == 2) ? N2 : (t == 1 ? N1 : N0);
    const __half* __restrict__ Bh = BhAll + wbase + (size_t)t * K * 512;

    float* __restrict__ C = (bn < 256) ? Cl : Cr;
    const int cb0 = bn & 255;

    float acc[2][8][4];
#pragma unroll
    for (int i = 0; i < 2; i++)
#pragma unroll
        for (int j = 0; j < 8; j++)
#pragma unroll
            for (int k = 0; k < 4; k++) acc[i][j][k] = 0.f;

    const int nc = K >> 5;

    auto load_chunk = [&](int c) {
        const uint32_t st = sb + (c % 3) * STAGE_B;
        const int k0 = c * KC;
#pragma unroll
        for (int it = 0; it < 2; it++) {
            int lin = tid + it * 256;
            int row = lin >> 2, seg = lin & 3;
            const char* gA = (const char*)(Ah + (size_t)(bm + row) * K + k0 + seg * 8);
            cp_async16(st + S_AH + row * (A_STR * 2) + seg * 16, gA);
        }
#pragma unroll
        for (int it = 0; it < 2; it++) {
            int lin = tid + it * 256;
            int row = lin >> 4, seg = lin & 15;
            const char* gH = (const char*)(Bh + (size_t)(k0 + row) * 512 + bn + seg * 8);
            cp_async16(st + S_BH + row * (B_STR * 2) + seg * 16, gH);
        }
    };

    load_chunk(0);
    cp_commit();
    if (nc > 1) { load_chunk(1); cp_commit(); }

    for (int c = 0; c < nc; c++) {
        if (c + 1 < nc) cp_wait<1>(); else cp_wait<0>();
        __syncthreads();

        const uint32_t st = sb + (c % 3) * STAGE_B;
#pragma unroll
        for (int ks = 0; ks < 2; ks++) {
            const int kk = ks * 16;
            uint32_t ah[2][4];
#pragma unroll
            for (int mt = 0; mt < 2; mt++) {
                uint32_t off = ((wm + mt * 16 + (lane & 15)) * A_STR + kk + (lane >> 4) * 8) * 2;
                ldmat_x4(st + S_AH + off, ah[mt][0], ah[mt][1], ah[mt][2], ah[mt][3]);
            }
            uint32_t bh[4][4];
#pragma unroll
            for (int np = 0; np < 4; np++) {
                uint32_t off = ((kk + (lane & 15)) * B_STR + wn + np * 16 + (lane >> 4) * 8) * 2;
                ldmat_x4_t(st + S_BH + off, bh[np][0], bh[np][1], bh[np][2], bh[np][3]);
            }
#pragma unroll
            for (int mt = 0; mt < 2; mt++)
#pragma unroll
                for (int np = 0; np < 4; np++)
#pragma unroll
                    for (int half = 0; half < 2; half++) {
                        int nt = np * 2 + half;
                        float* a = acc[mt][nt];
                        mma_f16(a[0], a[1], a[2], a[3],
                                ah[mt][0], ah[mt][1], ah[mt][2], ah[mt][3],
                                bh[np][half * 2], bh[np][half * 2 + 1]);
                    }
        }
        if (c + 2 < nc) { load_chunk(c + 2); cp_commit(); }
    }

    const int g4 = lane >> 2, t4 = lane & 3;
#pragma unroll
    for (int mt = 0; mt < 2; mt++) {
        int r0 = bm + wm + mt * 16 + g4;
        int r1 = r0 + 8;
#pragma unroll
        for (int nt = 0; nt < 8; nt++) {
            int col = cb0 + wn + nt * 8 + t4 * 2;
            if (r0 - Pt < Nt) *(float2*)(C + (size_t)r0 * 256 + col) =
                make_float2(acc[mt][nt][0], acc[mt][nt][1]);
            if (r1 - Pt < Nt) *(float2*)(C + (size_t)r1 * 256 + col) =
                make_float2(acc[mt][nt][2], acc[mt][nt][3]);
        }
    }
}

// ---------------- layer-1 split: x (3 ptrs) -> Ah [NPAD,128] fp16, pads zeroed ----------------
__global__ void split_x_kernel(const float* __restrict__ x0, const float* __restrict__ x1,
                               const float* __restrict__ x2,
                               __half* __restrict__ hi,
                               int P1, int P2, int N0, int N1, int N2, int NPAD) {
    int i = blockIdx.x * 256 + threadIdx.x;      // float4 index over NPAD*128
    if (i >= NPAD * 32) return;
    int row = i >> 5, q = i & 31;
    int t  = (row >= P2) ? 2 : (row >= P1 ? 1 : 0);
    int Pt = (t == 2) ? P2 : (t == 1 ? P1 : 0);
    int Nt = (t == 2) ? N2 : (t == 1 ? N1 : N0);
    const float* xp = (t == 2) ? x2 : (t == 1 ? x1 : x0);
    int lr = row - Pt;
    float4 v = make_float4(0.f, 0.f, 0.f, 0.f);
    if (lr < Nt) v = ((const float4*)xp)[lr * 32 + q];
    ((__half2*)hi)[2 * i]     = __halves2half2(__float2half(v.x), __float2half(v.y));
    ((__half2*)hi)[2 * i + 1] = __halves2half2(__float2half(v.z), __float2half(v.w));
}

// ---------------- pack ALL weights (both layers, 3 types) -> Bcat fp16 ----------------
__global__ void pack_weights_kernel(const float* __restrict__ Wl1, const float* __restrict__ Wr1,
                                    const float* __restrict__ Wl2, const float* __restrict__ Wr2,
                                    __half* __restrict__ th) {
    int idx = blockIdx.x * 256 + threadIdx.x;
    const int L1 = 3 * 128 * 512;
    const int TOT = L1 + 3 * 256 * 512;
    if (idx >= TOT) return;
    float v;
    if (idx < L1) {
        int t = idx / (128 * 512), rem = idx % (128 * 512);
        int k = rem >> 9, c = rem & 511;
        v = (c < 256) ? Wl1[(size_t)t * 128 * 256 + k * 256 + c]
                      : Wr1[(size_t)t * 128 * 256 + k * 256 + (c - 256)];
    } else {
        int j = idx - L1;
        int t = j / (256 * 512), rem = j % (256 * 512);
        int k = rem >> 9, c = rem & 511;
        v = (c < 256) ? Wl2[(size_t)t * 256 * 256 + k * 256 + c]
                      : Wr2[(size_t)t * 256 * 256 + k * 256 + (c - 256)];
    }
    th[idx] = __float2half(v);
}

// ---------------- CSR build (all types, global padded node ids) ----------------
__global__ void hist_kernel(const int* __restrict__ d0, const int* __restrict__ d1,
                            const int* __restrict__ d2, int* __restrict__ deg,
                            int E0, int E1, int E2, int P1, int P2) {
    int e = blockIdx.x * 256 + threadIdx.x;
    int dv;
    if (e < E0) dv = d0[e];
    else if (e < E0 + E1) dv = d1[e - E0] + P1;
    else if (e < E0 + E1 + E2) dv = d2[e - E0 - E1] + P2;
    else return;
    atomicAdd(&deg[dv], 1);
}

__global__ void scan_bsum_kernel(const int* __restrict__ deg, int* __restrict__ bsum, int N) {
    __shared__ int sh[256];
    int b = blockIdx.x, t = threadIdx.x;
    int s = 0;
    for (int j = t; j < 1024; j += 256) {
        int i = b * 1024 + j;
        if (i < N) s += deg[i];
    }
    sh[t] = s;
    __syncthreads();
    for (int off = 128; off > 0; off >>= 1) {
        if (t < off) sh[t] += sh[t + off];
        __syncthreads();
    }
    if (t == 0) bsum[b] = sh[0];
}

__global__ void scan_boff_kernel(int* __restrict__ bsum, int* __restrict__ rowptr,
                                 int nb, int N) {
    if (threadIdx.x == 0) {
        int acc = 0;
        for (int b = 0; b < nb; b++) { int v = bsum[b]; bsum[b] = acc; acc += v; }
        rowptr[N] = acc;
    }
}

__global__ void scan_final_kernel(const int* __restrict__ deg, const int* __restrict__ bsum,
                                  int* __restrict__ rowptr, int N) {
    __shared__ int sh[1024];
    int b = blockIdx.x, t = threadIdx.x;
    int i = b * 1024 + t;
    int v = (i < N) ? deg[i] : 0;
    sh[t] = v;
    __syncthreads();
    for (int off = 1; off < 1024; off <<= 1) {
        int u = (t >= off) ? sh[t - off] : 0;
        __syncthreads();
        sh[t] += u;
        __syncthreads();
    }
    if (i < N) rowptr[i] = bsum[b] + sh[t] - v;
}

__global__ void scatter_kernel(const int* __restrict__ s0, const int* __restrict__ d0,
                               const int* __restrict__ s1, const int* __restrict__ d1,
                               const int* __restrict__ s2, const int* __restrict__ d2,
                               const int* __restrict__ rowptr, int* __restrict__ cursor,
                               int* __restrict__ csrsrc,
                               int E0, int E1, int E2, int P1, int P2) {
    int e = blockIdx.x * 256 + threadIdx.x;
    int sv, dv;
    if (e < E0)                { sv = s0[e];            dv = d0[e]; }
    else if (e < E0 + E1)      { sv = s1[e - E0] + P1;  dv = d1[e - E0] + P1; }
    else if (e < E0 + E1 + E2) { sv = s2[e - E0 - E1] + P2; dv = d2[e - E0 - E1] + P2; }
    else return;
    int pos = atomicAdd(&cursor[dv], 1);
    csrsrc[rowptr[dv] + pos] = sv;
}

// ---------------- GATv2 aggregate (all types): one warp per dst node ----------------
// 2-edge unrolled: interleaved score/shfl chains + joint online-softmax update.
__global__ __launch_bounds__(256) void gat_kernel(
    const float* __restrict__ hl, const float* __restrict__ hr,
    const int* __restrict__ rowptr, const int* __restrict__ csrsrc,
    const float* __restrict__ attAll, const float* __restrict__ biasAll,
    float* __restrict__ out, int P1, int P2, int N0, int N1, int N2, int NPAD)
{
    int d = (blockIdx.x * blockDim.x + threadIdx.x) >> 5;
    if (d >= NPAD) return;
    int t  = (d >= P2) ? 2 : (d >= P1 ? 1 : 0);
    int Pt = (t == 2) ? P2 : (t == 1 ? P1 : 0);
    int Nt = (t == 2) ? N2 : (t == 1 ? N1 : N0);
    if (d - Pt >= Nt) return;                     // pad node
    int lane = threadIdx.x & 31;
    int base = lane * 8;
    const float* att  = attAll + t * 256;
    const float* bias = biasAll + t * 256;

    float4 at0 = *(const float4*)(att + base);
    float4 at1 = *(const float4*)(att + base + 4);
    float atv[8] = {at0.x, at0.y, at0.z, at0.w, at1.x, at1.y, at1.z, at1.w};

    const float* hrp = hr + (size_t)d * 256 + base;
    float4 r0 = *(const float4*)hrp;
    float4 r1 = *(const float4*)(hrp + 4);
    float hrv[8] = {r0.x, r0.y, r0.z, r0.w, r1.x, r1.y, r1.z, r1.w};

    float m = -1.0e30f, den = 0.f;
    float acc[8] = {0.f, 0.f, 0.f, 0.f, 0.f, 0.f, 0.f, 0.f};

    int e0 = rowptr[d], e1 = rowptr[d + 1];
    int e = e0 - 1;                               // e == e0-1 -> self loop

    for (; e + 1 < e1; e += 2) {
        int s0 = (e < e0) ? d : csrsrc[e];
        int s1 = csrsrc[e + 1];
        const float* hp0 = hl + (size_t)s0 * 256 + base;
        const float* hp1 = hl + (size_t)s1 * 256 + base;
        float4 a0 = *(const float4*)hp0;
        float4 a1 = *(const float4*)(hp0 + 4);
        float4 b0 = *(const float4*)hp1;
        float4 b1 = *(const float4*)(hp1 + 4);
        float hva[8] = {a0.x, a0.y, a0.z, a0.w, a1.x, a1.y, a1.z, a1.w};
        float hvb[8] = {b0.x, b0.y, b0.z, b0.w, b1.x, b1.y, b1.z, b1.w};

        float pa = 0.f, pb = 0.f;
#pragma unroll
        for (int j = 0; j < 8; j++) {
            float va = hva[j] + hrv[j];
            float vb = hvb[j] + hrv[j];
            va = (va > 0.f) ? va : 0.2f * va;
            vb = (vb > 0.f) ? vb : 0.2f * vb;
            pa += va * atv[j];
            pb += vb * atv[j];
        }
        pa += __shfl_xor_sync(0xffffffffu, pa, 1);
        pb += __shfl_xor_sync(0xffffffffu, pb, 1);
        pa += __shfl_xor_sync(0xffffffffu, pa, 2);
        pb += __shfl_xor_sync(0xffffffffu, pb, 2);
        pa += __shfl_xor_sync(0xffffffffu, pa, 4);
        pb += __shfl_xor_sync(0xffffffffu, pb, 4);

        float nm = fmaxf(m, fmaxf(pa, pb));
        float f  = __expf(m - nm);
        float wa = __expf(pa - nm);
        float wb = __expf(pb - nm);
        den = den * f + wa + wb;
        m = nm;
#pragma unroll
        for (int j = 0; j < 8; j++)
            acc[j] = acc[j] * f + wa * hva[j] + wb * hvb[j];
    }

    if (e < e1) {                                 // tail (single edge / lone self loop)
        int s = (e < e0) ? d : csrsrc[e];
        const float* hp = hl + (size_t)s * 256 + base;
        float4 h0 = *(const float4*)hp;
        float4 h1 = *(const float4*)(hp + 4);
        float hv[8] = {h0.x, h0.y, h0.z, h0.w, h1.x, h1.y, h1.z, h1.w};
        float p = 0.f;
#pragma unroll
        for (int j = 0; j < 8; j++) {
            float v = hv[j] + hrv[j];
            v = (v > 0.f) ? v : 0.2f * v;
            p += v * atv[j];
        }
        p += __shfl_xor_sync(0xffffffffu, p, 1);
        p += __shfl_xor_sync(0xffffffffu, p, 2);
        p += __shfl_xor_sync(0xffffffffu, p, 4);
        float nm = fmaxf(m, p);
        float f  = __expf(m - nm);
        float wv = __expf(p - nm);
        den = den * f + wv;
        m = nm;
#pragma unroll
        for (int j = 0; j < 8; j++) acc[j] = acc[j] * f + wv * hv[j];
    }

    float inv = 1.f / (den + 1e-16f);
    float* op = out + (size_t)d * 256 + base;
    float4 o0, o1;
    o0.x = acc[0] * inv + bias[base + 0];
    o0.y = acc[1] * inv + bias[base + 1];
    o0.z = acc[2] * inv + bias[base + 2];
    o0.w = acc[3] * inv + bias[base + 3];
    o1.x = acc[4] * inv + bias[base + 4];
    o1.y = acc[5] * inv + bias[base + 5];
    o1.z = acc[6] * inv + bias[base + 6];
    o1.w = acc[7] * inv + bias[base + 7];
    *(float4*)op       = o0;
    *(float4*)(op + 4) = o1;
}

// ---------------- BatchNorm (per-type stats, grid.y = type) ----------------
__global__ void bn_stats_kernel(const float* __restrict__ x,
                                float* __restrict__ bnsum, float* __restrict__ bnsq,
                                int P1, int P2, int N0, int N1, int N2) {
    int t = blockIdx.y;
    int Pt = (t == 2) ? P2 : (t == 1 ? P1 : 0);
    int Nt = (t == 2) ? N2 : (t == 1 ? N1 : N0);
    int c = threadIdx.x;
    float s = 0.f, q = 0.f;
    for (int r = blockIdx.x; r < Nt; r += gridDim.x) {
        float v = x[(size_t)(Pt + r) * 256 + c];
        s += v;
        q += v * v;
    }
    atomicAdd(&bnsum[t * 256 + c], s);
    atomicAdd(&bnsq[t * 256 + c], q);
}

__global__ void bn_final_kernel(const float* __restrict__ bnsum, const float* __restrict__ bnsq,
                                const float* __restrict__ g, const float* __restrict__ b,
                                float* __restrict__ scale, float* __restrict__ shift,
                                int N0, int N1, int N2) {
    int c = threadIdx.x + blockIdx.x * 256;      // 0..767
    int t = c >> 8;
    int Nt = (t == 2) ? N2 : (t == 1 ? N1 : N0);
    float invn = 1.f / (float)Nt;
    float mean = bnsum[c] * invn;
    float var  = bnsq[c] * invn - mean * mean;
    float sc   = g[c] * rsqrtf(var + 1e-5f);
    scale[c] = sc;
    shift[c] = b[c] - mean * sc;
}

// bn + leaky-relu; do_split -> emit fp16 for next GEMM; do_store -> write fp32 hn
__global__ void bn_apply_kernel(const float* __restrict__ in, float* __restrict__ outp,
                                __half* __restrict__ oh,
                                const float* __restrict__ scale, const float* __restrict__ shift,
                                int P1, int P2, int NPAD, int do_split, int do_store) {
    int i = blockIdx.x * 256 + threadIdx.x;      // float4 over NPAD*256
    if (i >= NPAD * 64) return;
    int row = i >> 6;
    int t = (row >= P2) ? 2 : (row >= P1 ? 1 : 0);
    int c = t * 256 + (i & 63) * 4;
    float4 v  = *(const float4*)(in + (size_t)i * 4);
    float4 sc = *(const float4*)(scale + c);
    float4 sh = *(const float4*)(shift + c);
    float a0 = v.x * sc.x + sh.x;
    float a1 = v.y * sc.y + sh.y;
    float a2 = v.z * sc.z + sh.z;
    float a3 = v.w * sc.w + sh.w;
    float4 o;
    o.x = (a0 > 0.f) ? a0 : 0.01f * a0;
    o.y = (a1 > 0.f) ? a1 : 0.01f * a1;
    o.z = (a2 > 0.f) ? a2 : 0.01f * a2;
    o.w = (a3 > 0.f) ? a3 : 0.01f * a3;
    if (do_store) *(float4*)(outp + (size_t)i * 4) = o;
    if (do_split) {
        ((__half2*)oh)[2 * i]     = __halves2half2(__float2half(o.x), __float2half(o.y));
        ((__half2*)oh)[2 * i + 1] = __halves2half2(__float2half(o.z), __float2half(o.w));
    }
}

// ---------------- Classifier: warp per (compact) output row ----------------
__global__ __launch_bounds__(256) void classifier_kernel(
    const float* __restrict__ h, const float* __restrict__ cW,
    const float* __restrict__ cb, float* __restrict__ outp,
    int P1, int P2, int N0, int N1, int N2)
{
    int idx = (blockIdx.x * blockDim.x + threadIdx.x) >> 5;    // compact row
    int NT = N0 + N1 + N2;
    if (idx >= NT) return;
    int t  = (idx >= N0 + N1) ? 2 : (idx >= N0 ? 1 : 0);
    int Ct = (t == 2) ? N0 + N1 : (t == 1 ? N0 : 0);
    int Pt = (t == 2) ? P2 : (t == 1 ? P1 : 0);
    int row = Pt + (idx - Ct);
    int lane = threadIdx.x & 31;

    const float* hp = h + (size_t)row * 256 + lane * 8;
    float4 h0 = *(const float4*)hp;
    float4 h1 = *(const float4*)(hp + 4);
    float hv[8] = {h0.x, h0.y, h0.z, h0.w, h1.x, h1.y, h1.z, h1.w};

    const float* wp = cW + lane * 16;
    float4 w0 = *(const float4*)(wp + 0);
    float4 w1 = *(const float4*)(wp + 4);
    float4 w2 = *(const float4*)(wp + 8);
    float4 w3 = *(const float4*)(wp + 12);
    float wv[16] = {w0.x, w0.y, w0.z, w0.w, w1.x, w1.y, w1.z, w1.w,
                    w2.x, w2.y, w2.z, w2.w, w3.x, w3.y, w3.z, w3.w};

    float c0 = 0.f, c1 = 0.f;
#pragma unroll
    for (int j = 0; j < 8; j++) {
        c0 += hv[j] * wv[2 * j];
        c1 += hv[j] * wv[2 * j + 1];
    }
#pragma unroll
    for (int off = 16; off > 0; off >>= 1) {
        c0 += __shfl_xor_sync(0xffffffffu, c0, off);
        c1 += __shfl_xor_sync(0xffffffffu, c1, off);
    }
    if (lane == 0) {
        outp[(size_t)idx * 2 + 0] = c0 + cb[0];
        outp[(size_t)idx * 2 + 1] = c1 + cb[1];
    }
}

// ---------------- launch ----------------
extern "C" void kernel_launch(void* const* d_in, const int* in_sizes, int n_in,
                              void* d_out, int out_size) {
    const float* x[3];
    const int*   ei[3];
    for (int i = 0; i < 3; i++) {
        x[i]  = (const float*)d_in[i];
        ei[i] = (const int*)d_in[3 + i];
    }
    const float* Wl1  = (const float*)d_in[6];
    const float* Wr1  = (const float*)d_in[7];
    const float* att1 = (const float*)d_in[8];
    const float* b1   = (const float*)d_in[9];
    const float* Wl2  = (const float*)d_in[10];
    const float* Wr2  = (const float*)d_in[11];
    const float* att2 = (const float*)d_in[12];
    const float* b2   = (const float*)d_in[13];
    const float* bng  = (const float*)d_in[14];
    const float* bnb  = (const float*)d_in[15];
    const float* cW   = (const float*)d_in[16];
    const float* cb   = (const float*)d_in[17];
    float* out = (float*)d_out;

    float *hl, *hr, *h, *hn, *bnsum, *bnsq, *scale, *shift;
    __half *Ah, *Bh;
    int *rowptr, *csrsrc, *deg, *cursor, *bsum;
    cudaGetSymbolAddress((void**)&hl,     g_hl);
    cudaGetSymbolAddress((void**)&hr,     g_hr);
    cudaGetSymbolAddress((void**)&h,      g_h);
    cudaGetSymbolAddress((void**)&hn,     g_hn);
    cudaGetSymbolAddress((void**)&Ah,     g_Ah);
    cudaGetSymbolAddress((void**)&Bh,     g_Bh);
    cudaGetSymbolAddress((void**)&rowptr, g_rowptr);
    cudaGetSymbolAddress((void**)&csrsrc, g_csrsrc);
    cudaGetSymbolAddress((void**)&deg,    g_deg);
    cudaGetSymbolAddress((void**)&cursor, g_cursor);
    cudaGetSymbolAddress((void**)&bsum,   g_bsum);
    cudaGetSymbolAddress((void**)&bnsum,  g_bnsum);
    cudaGetSymbolAddress((void**)&bnsq,   g_bnsq);
    cudaGetSymbolAddress((void**)&scale,  g_scale);
    cudaGetSymbolAddress((void**)&shift,  g_shift);

    cudaFuncSetAttribute(gemm_mma_kernel,
                         cudaFuncAttributeMaxDynamicSharedMemorySize, GEMM_SMEM);

    // geometry
    int N0 = in_sizes[0] / 128, N1 = in_sizes[1] / 128, N2 = in_sizes[2] / 128;
    int E0 = in_sizes[3] / 2,   E1 = in_sizes[4] / 2,   E2 = in_sizes[5] / 2;
    int T0 = (N0 + 127) / 128, T1 = (N1 + 127) / 128, T2 = (N2 + 127) / 128;
    int P1 = T0 * 128, P2 = P1 + T1 * 128;
    int NPAD = P2 + T2 * 128;
    int ET = E0 + E1 + E2;
    int ntile = NPAD / 128;
    int nb = (NPAD + 1023) / 1024;

    // --- prep; layer-1 GEMM at launch index 4 so ncu profiles it ---
    split_x_kernel<<<(NPAD * 32 + 255) / 256, 256>>>(x[0], x[1], x[2], Ah,
                                                     P1, P2, N0, N1, N2, NPAD);   // 0
    {
        int tot = 3 * 128 * 512 + 3 * 256 * 512;
        pack_weights_kernel<<<(tot + 255) / 256, 256>>>(Wl1, Wr1, Wl2, Wr2, Bh);  // 1
    }
    cudaMemsetAsync(deg, 0, NPAD * sizeof(int), 0);                               // 2
    hist_kernel<<<(ET + 255) / 256, 256>>>(ei[0] + E0, ei[1] + E1, ei[2] + E2,
                                           deg, E0, E1, E2, P1, P2);              // 3

    dim3 gg(4, ntile);
    gemm_mma_kernel<<<gg, 256, GEMM_SMEM>>>(Ah, Bh, hl, hr,
                                            P1, P2, N0, N1, N2, 128, 0);          // 4 (profiled)

    scan_bsum_kernel<<<nb, 256>>>(deg, bsum, NPAD);
    scan_boff_kernel<<<1, 32>>>(bsum, rowptr, nb, NPAD);
    scan_final_kernel<<<nb, 1024>>>(deg, bsum, rowptr, NPAD);
    cudaMemsetAsync(cursor, 0, NPAD * sizeof(int), 0);
    scatter_kernel<<<(ET + 255) / 256, 256>>>(ei[0], ei[0] + E0, ei[1], ei[1] + E1,
                                              ei[2], ei[2] + E2,
                                              rowptr, cursor, csrsrc, E0, E1, E2, P1, P2);

    for (int layer = 0; layer < 2; layer++) {
        if (layer == 1) {
            gemm_mma_kernel<<<gg, 256, GEMM_SMEM>>>(Ah, Bh, hl, hr,
                                                    P1, P2, N0, N1, N2, 256, L2_WOFF);
        }
        const float* at = (layer == 0) ? att1 : att2;
        const float* bs = (layer == 0) ? b1 : b2;

        gat_kernel<<<(NPAD * 32 + 255) / 256, 256>>>(hl, hr, rowptr, csrsrc, at, bs, h,
                                                     P1, P2, N0, N1, N2, NPAD);

        cudaMemsetAsync(bnsum, 0, 768 * sizeof(float), 0);
        cudaMemsetAsync(bnsq,  0, 768 * sizeof(float), 0);
        {
            dim3 gs(128, 3);
            bn_stats_kernel<<<gs, 256>>>(h, bnsum, bnsq, P1, P2, N0, N1, N2);
        }
        bn_final_kernel<<<3, 256>>>(bnsum, bnsq, bng, bnb, scale, shift, N0, N1, N2);
        bn_apply_kernel<<<(NPAD * 64 + 255) / 256, 256>>>(
            h, hn, Ah, scale, shift, P1, P2, NPAD,
            layer == 0 ? 1 : 0, layer == 0 ? 0 : 1);
    }

    classifier_kernel<<<((N0 + N1 + N2) * 32 + 255) / 256, 256>>>(
        hn, cW, cb, out, P1, P2, N0, N1, N2);
}

// round 17
// speedup vs baseline: 1.3607x; 1.3607x over previous
#include <cuda_runtime.h>
#include <cuda_fp16.h>
#include <math.h>
#include <stdint.h>

// ---------------- static scratch (no runtime allocation allowed) ----------------
#define MAXN 50000
#define NPADMAX (3 * 50048)          // per-type padded to 128 rows
#define MAXET (3 * 400000)

__device__ float g_hl[NPADMAX * 256];
__device__ float g_hr[NPADMAX * 256];
__device__ float g_h [NPADMAX * 256];
__device__ float g_hn[NPADMAX * 256];
__device__ __half g_Ah[NPADMAX * 256];
__device__ __half g_Bh[3 * (128 + 256) * 512];
__device__ int   g_rowptr[NPADMAX + 1];
__device__ int   g_csrsrc[MAXET];
__device__ int   g_deg[NPADMAX];
__device__ int   g_cursor[NPADMAX];
__device__ int   g_bsum[256];
__device__ float g_bnsum[768];
__device__ float g_bnsq[768];
__device__ float g_scale[768];
__device__ float g_shift[768];

#define L2_WOFF (3 * 128 * 512)      // offset of layer-2 weights inside g_Bh

// ---------------- baseline-PTX helpers (no 'a'-suffix features) ----------------
__device__ __forceinline__ uint32_t smem_u32(const void* p) {
    uint32_t a;
    asm("{ .reg .u64 t; cvta.to.shared.u64 t, %1; cvt.u32.u64 %0, t; }" : "=r"(a) : "l"(p));
    return a;
}
__device__ __forceinline__ void cp_async16(uint32_t dst, const void* src) {
    asm volatile("cp.async.cg.shared.global [%0], [%1], 16;" :: "r"(dst), "l"(src));
}
__device__ __forceinline__ void cp_commit() { asm volatile("cp.async.commit_group;" ::: "memory"); }
template <int N>
__device__ __forceinline__ void cp_wait() { asm volatile("cp.async.wait_group %0;" :: "n"(N) : "memory"); }

__device__ __forceinline__ void ldmat_x4(uint32_t addr, uint32_t& r0, uint32_t& r1,
                                         uint32_t& r2, uint32_t& r3) {
    asm volatile("ldmatrix.sync.aligned.m8n8.x4.shared.b16 {%0,%1,%2,%3}, [%4];"
                 : "=r"(r0), "=r"(r1), "=r"(r2), "=r"(r3) : "r"(addr));
}
__device__ __forceinline__ void ldmat_x4_t(uint32_t addr, uint32_t& r0, uint32_t& r1,
                                           uint32_t& r2, uint32_t& r3) {
    asm volatile("ldmatrix.sync.aligned.m8n8.x4.trans.shared.b16 {%0,%1,%2,%3}, [%4];"
                 : "=r"(r0), "=r"(r1), "=r"(r2), "=r"(r3) : "r"(addr));
}
__device__ __forceinline__ void mma_f16(float& c0, float& c1, float& c2, float& c3,
                                        uint32_t a0, uint32_t a1, uint32_t a2, uint32_t a3,
                                        uint32_t b0, uint32_t b1) {
    asm volatile("mma.sync.aligned.m16n8k16.row.col.f32.f16.f16.f32 "
                 "{%0,%1,%2,%3}, {%4,%5,%6,%7}, {%8,%9}, {%0,%1,%2,%3};"
                 : "+f"(c0), "+f"(c1), "+f"(c2), "+f"(c3)
                 : "r"(a0), "r"(a1), "r"(a2), "r"(a3), "r"(b0), "r"(b1));
}

// ---------------- HMMA GEMM: [hl|hr][M,256] = A[Mpad,K] @ Bcat_type[K,512] ----------------
// Single-fp16 A and B. 2-stage double buffer (R15-proven ordering).
// SMEM per stage: Ah[128][40]h @0, Bh[32][136]h @10240
#define KC 32
#define A_STR 40
#define B_STR 136
#define S_AH 0
#define S_BH 10240
#define STAGE_B 18944
#define GEMM_SMEM (2 * STAGE_B)

__global__ __launch_bounds__(256) void gemm_mma_kernel(
    const __half* __restrict__ Ah, const __half* __restrict__ BhAll,
    float* __restrict__ Cl, float* __restrict__ Cr,
    int P1, int P2, int N0, int N1, int N2, int K, int wbase)
{
    extern __shared__ char smem[];
    const uint32_t sb = smem_u32(smem);
    const int tid  = threadIdx.x;
    const int lane = tid & 31;
    const int w    = tid >> 5;
    const int wm   = (w & 3) * 32;
    const int wn   = (w >> 2) * 64;
    const int bm   = blockIdx.y * 128;
    const int bn   = blockIdx.x * 128;   // within 512 concat cols

    const int t  = (bm >= P2) ? 2 : (bm >= P1 ? 1 : 0);
    const int Pt = (t == 2) ? P2 : (t == 1 ? P1 : 0);
    const int Nt = (t == 2) ? N2 : (t == 1 ? N1 : N0);
    const __half* __restrict__ Bh = BhAll + wbase + (size_t)t * K * 512;

    float* __restrict__ C = (bn < 256) ? Cl : Cr;
    const int cb0 = bn & 255;

    float acc[2][8][4];
#pragma unroll
    for (int i = 0; i < 2; i++)
#pragma unroll
        for (int j = 0; j < 8; j++)
#pragma unroll
            for (int k = 0; k < 4; k++) acc[i][j][k] = 0.f;

    const int nc = K >> 5;

    auto load_chunk = [&](int c) {
        const uint32_t st = sb + (c & 1) * STAGE_B;
        const int k0 = c * KC;
#pragma unroll
        for (int it = 0; it < 2; it++) {
            int lin = tid + it * 256;
            int row = lin >> 2, seg = lin & 3;
            const char* gA = (const char*)(Ah + (size_t)(bm + row) * K + k0 + seg * 8);
            cp_async16(st + S_AH + row * (A_STR * 2) + seg * 16, gA);
        }
#pragma unroll
        for (int it = 0; it < 2; it++) {
            int lin = tid + it * 256;
            int row = lin >> 4, seg = lin & 15;
            const char* gH = (const char*)(Bh + (size_t)(k0 + row) * 512 + bn + seg * 8);
            cp_async16(st + S_BH + row * (B_STR * 2) + seg * 16, gH);
        }
    };

    load_chunk(0);
    cp_commit();

    for (int c = 0; c < nc; c++) {
        if (c + 1 < nc) { load_chunk(c + 1); cp_commit(); cp_wait<1>(); }
        else            { cp_wait<0>(); }
        __syncthreads();

        const uint32_t st = sb + (c & 1) * STAGE_B;
#pragma unroll
        for (int ks = 0; ks < 2; ks++) {
            const int kk = ks * 16;
            uint32_t ah[2][4];
#pragma unroll
            for (int mt = 0; mt < 2; mt++) {
                uint32_t off = ((wm + mt * 16 + (lane & 15)) * A_STR + kk + (lane >> 4) * 8) * 2;
                ldmat_x4(st + S_AH + off, ah[mt][0], ah[mt][1], ah[mt][2], ah[mt][3]);
            }
            uint32_t bh[4][4];
#pragma unroll
            for (int np = 0; np < 4; np++) {
                uint32_t off = ((kk + (lane & 15)) * B_STR + wn + np * 16 + (lane >> 4) * 8) * 2;
                ldmat_x4_t(st + S_BH + off, bh[np][0], bh[np][1], bh[np][2], bh[np][3]);
            }
#pragma unroll
            for (int mt = 0; mt < 2; mt++)
#pragma unroll
                for (int np = 0; np < 4; np++)
#pragma unroll
                    for (int half = 0; half < 2; half++) {
                        int nt = np * 2 + half;
                        float* a = acc[mt][nt];
                        mma_f16(a[0], a[1], a[2], a[3],
                                ah[mt][0], ah[mt][1], ah[mt][2], ah[mt][3],
                                bh[np][half * 2], bh[np][half * 2 + 1]);
                    }
        }
        __syncthreads();
    }

    const int g4 = lane >> 2, t4 = lane & 3;
#pragma unroll
    for (int mt = 0; mt < 2; mt++) {
        int r0 = bm + wm + mt * 16 + g4;
        int r1 = r0 + 8;
#pragma unroll
        for (int nt = 0; nt < 8; nt++) {
            int col = cb0 + wn + nt * 8 + t4 * 2;
            if (r0 - Pt < Nt) *(float2*)(C + (size_t)r0 * 256 + col) =
                make_float2(acc[mt][nt][0], acc[mt][nt][1]);
            if (r1 - Pt < Nt) *(float2*)(C + (size_t)r1 * 256 + col) =
                make_float2(acc[mt][nt][2], acc[mt][nt][3]);
        }
    }
}

// ---------------- layer-1 split: x (3 ptrs) -> Ah [NPAD,128] fp16, pads zeroed ----------------
__global__ void split_x_kernel(const float* __restrict__ x0, const float* __restrict__ x1,
                               const float* __restrict__ x2,
                               __half* __restrict__ hi,
                               int P1, int P2, int N0, int N1, int N2, int NPAD) {
    int i = blockIdx.x * 256 + threadIdx.x;      // float4 index over NPAD*128
    if (i >= NPAD * 32) return;
    int row = i >> 5, q = i & 31;
    int t  = (row >= P2) ? 2 : (row >= P1 ? 1 : 0);
    int Pt = (t == 2) ? P2 : (t == 1 ? P1 : 0);
    int Nt = (t == 2) ? N2 : (t == 1 ? N1 : N0);
    const float* xp = (t == 2) ? x2 : (t == 1 ? x1 : x0);
    int lr = row - Pt;
    float4 v = make_float4(0.f, 0.f, 0.f, 0.f);
    if (lr < Nt) v = ((const float4*)xp)[lr * 32 + q];
    ((__half2*)hi)[2 * i]     = __halves2half2(__float2half(v.x), __float2half(v.y));
    ((__half2*)hi)[2 * i + 1] = __halves2half2(__float2half(v.z), __float2half(v.w));
}

// ---------------- pack ALL weights (both layers, 3 types) -> Bcat fp16 ----------------
__global__ void pack_weights_kernel(const float* __restrict__ Wl1, const float* __restrict__ Wr1,
                                    const float* __restrict__ Wl2, const float* __restrict__ Wr2,
                                    __half* __restrict__ th) {
    int idx = blockIdx.x * 256 + threadIdx.x;
    const int L1 = 3 * 128 * 512;
    const int TOT = L1 + 3 * 256 * 512;
    if (idx >= TOT) return;
    float v;
    if (idx < L1) {
        int t = idx / (128 * 512), rem = idx % (128 * 512);
        int k = rem >> 9, c = rem & 511;
        v = (c < 256) ? Wl1[(size_t)t * 128 * 256 + k * 256 + c]
                      : Wr1[(size_t)t * 128 * 256 + k * 256 + (c - 256)];
    } else {
        int j = idx - L1;
        int t = j / (256 * 512), rem = j % (256 * 512);
        int k = rem >> 9, c = rem & 511;
        v = (c < 256) ? Wl2[(size_t)t * 256 * 256 + k * 256 + c]
                      : Wr2[(size_t)t * 256 * 256 + k * 256 + (c - 256)];
    }
    th[idx] = __float2half(v);
}

// ---------------- CSR build (all types, global padded node ids) ----------------
__global__ void hist_kernel(const int* __restrict__ d0, const int* __restrict__ d1,
                            const int* __restrict__ d2, int* __restrict__ deg,
                            int E0, int E1, int E2, int P1, int P2) {
    int e = blockIdx.x * 256 + threadIdx.x;
    int dv;
    if (e < E0) dv = d0[e];
    else if (e < E0 + E1) dv = d1[e - E0] + P1;
    else if (e < E0 + E1 + E2) dv = d2[e - E0 - E1] + P2;
    else return;
    atomicAdd(&deg[dv], 1);
}

__global__ void scan_bsum_kernel(const int* __restrict__ deg, int* __restrict__ bsum, int N) {
    __shared__ int sh[256];
    int b = blockIdx.x, t = threadIdx.x;
    int s = 0;
    for (int j = t; j < 1024; j += 256) {
        int i = b * 1024 + j;
        if (i < N) s += deg[i];
    }
    sh[t] = s;
    __syncthreads();
    for (int off = 128; off > 0; off >>= 1) {
        if (t < off) sh[t] += sh[t + off];
        __syncthreads();
    }
    if (t == 0) bsum[b] = sh[0];
}

__global__ void scan_boff_kernel(int* __restrict__ bsum, int* __restrict__ rowptr,
                                 int nb, int N) {
    if (threadIdx.x == 0) {
        int acc = 0;
        for (int b = 0; b < nb; b++) { int v = bsum[b]; bsum[b] = acc; acc += v; }
        rowptr[N] = acc;
    }
}

__global__ void scan_final_kernel(const int* __restrict__ deg, const int* __restrict__ bsum,
                                  int* __restrict__ rowptr, int N) {
    __shared__ int sh[1024];
    int b = blockIdx.x, t = threadIdx.x;
    int i = b * 1024 + t;
    int v = (i < N) ? deg[i] : 0;
    sh[t] = v;
    __syncthreads();
    for (int off = 1; off < 1024; off <<= 1) {
        int u = (t >= off) ? sh[t - off] : 0;
        __syncthreads();
        sh[t] += u;
        __syncthreads();
    }
    if (i < N) rowptr[i] = bsum[b] + sh[t] - v;
}

__global__ void scatter_kernel(const int* __restrict__ s0, const int* __restrict__ d0,
                               const int* __restrict__ s1, const int* __restrict__ d1,
                               const int* __restrict__ s2, const int* __restrict__ d2,
                               const int* __restrict__ rowptr, int* __restrict__ cursor,
                               int* __restrict__ csrsrc,
                               int E0, int E1, int E2, int P1, int P2) {
    int e = blockIdx.x * 256 + threadIdx.x;
    int sv, dv;
    if (e < E0)                { sv = s0[e];            dv = d0[e]; }
    else if (e < E0 + E1)      { sv = s1[e - E0] + P1;  dv = d1[e - E0] + P1; }
    else if (e < E0 + E1 + E2) { sv = s2[e - E0 - E1] + P2; dv = d2[e - E0 - E1] + P2; }
    else return;
    int pos = atomicAdd(&cursor[dv], 1);
    csrsrc[rowptr[dv] + pos] = sv;
}

// ---------------- GATv2 aggregate (all types): one warp per dst node ----------------
// 2-edge unrolled: interleaved score/shfl chains + joint online-softmax update.
__global__ __launch_bounds__(256) void gat_kernel(
    const float* __restrict__ hl, const float* __restrict__ hr,
    const int* __restrict__ rowptr, const int* __restrict__ csrsrc,
    const float* __restrict__ attAll, const float* __restrict__ biasAll,
    float* __restrict__ out, int P1, int P2, int N0, int N1, int N2, int NPAD)
{
    int d = (blockIdx.x * blockDim.x + threadIdx.x) >> 5;
    if (d >= NPAD) return;
    int t  = (d >= P2) ? 2 : (d >= P1 ? 1 : 0);
    int Pt = (t == 2) ? P2 : (t == 1 ? P1 : 0);
    int Nt = (t == 2) ? N2 : (t == 1 ? N1 : N0);
    if (d - Pt >= Nt) return;                     // pad node
    int lane = threadIdx.x & 31;
    int base = lane * 8;
    const float* att  = attAll + t * 256;
    const float* bias = biasAll + t * 256;

    float4 at0 = *(const float4*)(att + base);
    float4 at1 = *(const float4*)(att + base + 4);
    float atv[8] = {at0.x, at0.y, at0.z, at0.w, at1.x, at1.y, at1.z, at1.w};

    const float* hrp = hr + (size_t)d * 256 + base;
    float4 r0 = *(const float4*)hrp;
    float4 r1 = *(const float4*)(hrp + 4);
    float hrv[8] = {r0.x, r0.y, r0.z, r0.w, r1.x, r1.y, r1.z, r1.w};

    float m = -1.0e30f, den = 0.f;
    float acc[8] = {0.f, 0.f, 0.f, 0.f, 0.f, 0.f, 0.f, 0.f};

    int e0 = rowptr[d], e1 = rowptr[d + 1];
    int e = e0 - 1;                               // e == e0-1 -> self loop

    for (; e + 1 < e1; e += 2) {
        int s0 = (e < e0) ? d : csrsrc[e];
        int s1 = csrsrc[e + 1];
        const float* hp0 = hl + (size_t)s0 * 256 + base;
        const float* hp1 = hl + (size_t)s1 * 256 + base;
        float4 a0 = *(const float4*)hp0;
        float4 a1 = *(const float4*)(hp0 + 4);
        float4 b0 = *(const float4*)hp1;
        float4 b1 = *(const float4*)(hp1 + 4);
        float hva[8] = {a0.x, a0.y, a0.z, a0.w, a1.x, a1.y, a1.z, a1.w};
        float hvb[8] = {b0.x, b0.y, b0.z, b0.w, b1.x, b1.y, b1.z, b1.w};

        float pa = 0.f, pb = 0.f;
#pragma unroll
        for (int j = 0; j < 8; j++) {
            float va = hva[j] + hrv[j];
            float vb = hvb[j] + hrv[j];
            va = (va > 0.f) ? va : 0.2f * va;
            vb = (vb > 0.f) ? vb : 0.2f * vb;
            pa += va * atv[j];
            pb += vb * atv[j];
        }
        pa += __shfl_xor_sync(0xffffffffu, pa, 1);
        pb += __shfl_xor_sync(0xffffffffu, pb, 1);
        pa += __shfl_xor_sync(0xffffffffu, pa, 2);
        pb += __shfl_xor_sync(0xffffffffu, pb, 2);
        pa += __shfl_xor_sync(0xffffffffu, pa, 4);
        pb += __shfl_xor_sync(0xffffffffu, pb, 4);

        float nm = fmaxf(m, fmaxf(pa, pb));
        float f  = __expf(m - nm);
        float wa = __expf(pa - nm);
        float wb = __expf(pb - nm);
        den = den * f + wa + wb;
        m = nm;
#pragma unroll
        for (int j = 0; j < 8; j++)
            acc[j] = acc[j] * f + wa * hva[j] + wb * hvb[j];
    }

    if (e < e1) {                                 // tail (single edge / lone self loop)
        int s = (e < e0) ? d : csrsrc[e];
        const float* hp = hl + (size_t)s * 256 + base;
        float4 h0 = *(const float4*)hp;
        float4 h1 = *(const float4*)(hp + 4);
        float hv[8] = {h0.x, h0.y, h0.z, h0.w, h1.x, h1.y, h1.z, h1.w};
        float p = 0.f;
#pragma unroll
        for (int j = 0; j < 8; j++) {
            float v = hv[j] + hrv[j];
            v = (v > 0.f) ? v : 0.2f * v;
            p += v * atv[j];
        }
        p += __shfl_xor_sync(0xffffffffu, p, 1);
        p += __shfl_xor_sync(0xffffffffu, p, 2);
        p += __shfl_xor_sync(0xffffffffu, p, 4);
        float nm = fmaxf(m, p);
        float f  = __expf(m - nm);
        float wv = __expf(p - nm);
        den = den * f + wv;
        m = nm;
#pragma unroll
        for (int j = 0; j < 8; j++) acc[j] = acc[j] * f + wv * hv[j];
    }

    float inv = 1.f / (den + 1e-16f);
    float* op = out + (size_t)d * 256 + base;
    float4 o0, o1;
    o0.x = acc[0] * inv + bias[base + 0];
    o0.y = acc[1] * inv + bias[base + 1];
    o0.z = acc[2] * inv + bias[base + 2];
    o0.w = acc[3] * inv + bias[base + 3];
    o1.x = acc[4] * inv + bias[base + 4];
    o1.y = acc[5] * inv + bias[base + 5];
    o1.z = acc[6] * inv + bias[base + 6];
    o1.w = acc[7] * inv + bias[base + 7];
    *(float4*)op       = o0;
    *(float4*)(op + 4) = o1;
}

// ---------------- BatchNorm (per-type stats, grid.y = type) ----------------
__global__ void bn_stats_kernel(const float* __restrict__ x,
                                float* __restrict__ bnsum, float* __restrict__ bnsq,
                                int P1, int P2, int N0, int N1, int N2) {
    int t = blockIdx.y;
    int Pt = (t == 2) ? P2 : (t == 1 ? P1 : 0);
    int Nt = (t == 2) ? N2 : (t == 1 ? N1 : N0);
    int c = threadIdx.x;
    float s = 0.f, q = 0.f;
    for (int r = blockIdx.x; r < Nt; r += gridDim.x) {
        float v = x[(size_t)(Pt + r) * 256 + c];
        s += v;
        q += v * v;
    }
    atomicAdd(&bnsum[t * 256 + c], s);
    atomicAdd(&bnsq[t * 256 + c], q);
}

__global__ void bn_final_kernel(const float* __restrict__ bnsum, const float* __restrict__ bnsq,
                                const float* __restrict__ g, const float* __restrict__ b,
                                float* __restrict__ scale, float* __restrict__ shift,
                                int N0, int N1, int N2) {
    int c = threadIdx.x + blockIdx.x * 256;      // 0..767
    int t = c >> 8;
    int Nt = (t == 2) ? N2 : (t == 1 ? N1 : N0);
    float invn = 1.f / (float)Nt;
    float mean = bnsum[c] * invn;
    float var  = bnsq[c] * invn - mean * mean;
    float sc   = g[c] * rsqrtf(var + 1e-5f);
    scale[c] = sc;
    shift[c] = b[c] - mean * sc;
}

// bn + leaky-relu; do_split -> emit fp16 for next GEMM; do_store -> write fp32 hn
__global__ void bn_apply_kernel(const float* __restrict__ in, float* __restrict__ outp,
                                __half* __restrict__ oh,
                                const float* __restrict__ scale, const float* __restrict__ shift,
                                int P1, int P2, int NPAD, int do_split, int do_store) {
    int i = blockIdx.x * 256 + threadIdx.x;      // float4 over NPAD*256
    if (i >= NPAD * 64) return;
    int row = i >> 6;
    int t = (row >= P2) ? 2 : (row >= P1 ? 1 : 0);
    int c = t * 256 + (i & 63) * 4;
    float4 v  = *(const float4*)(in + (size_t)i * 4);
    float4 sc = *(const float4*)(scale + c);
    float4 sh = *(const float4*)(shift + c);
    float a0 = v.x * sc.x + sh.x;
    float a1 = v.y * sc.y + sh.y;
    float a2 = v.z * sc.z + sh.z;
    float a3 = v.w * sc.w + sh.w;
    float4 o;
    o.x = (a0 > 0.f) ? a0 : 0.01f * a0;
    o.y = (a1 > 0.f) ? a1 : 0.01f * a1;
    o.z = (a2 > 0.f) ? a2 : 0.01f * a2;
    o.w = (a3 > 0.f) ? a3 : 0.01f * a3;
    if (do_store) *(float4*)(outp + (size_t)i * 4) = o;
    if (do_split) {
        ((__half2*)oh)[2 * i]     = __halves2half2(__float2half(o.x), __float2half(o.y));
        ((__half2*)oh)[2 * i + 1] = __halves2half2(__float2half(o.z), __float2half(o.w));
    }
}

// ---------------- Classifier: warp per (compact) output row ----------------
__global__ __launch_bounds__(256) void classifier_kernel(
    const float* __restrict__ h, const float* __restrict__ cW,
    const float* __restrict__ cb, float* __restrict__ outp,
    int P1, int P2, int N0, int N1, int N2)
{
    int idx = (blockIdx.x * blockDim.x + threadIdx.x) >> 5;    // compact row
    int NT = N0 + N1 + N2;
    if (idx >= NT) return;
    int t  = (idx >= N0 + N1) ? 2 : (idx >= N0 ? 1 : 0);
    int Ct = (t == 2) ? N0 + N1 : (t == 1 ? N0 : 0);
    int Pt = (t == 2) ? P2 : (t == 1 ? P1 : 0);
    int row = Pt + (idx - Ct);
    int lane = threadIdx.x & 31;

    const float* hp = h + (size_t)row * 256 + lane * 8;
    float4 h0 = *(const float4*)hp;
    float4 h1 = *(const float4*)(hp + 4);
    float hv[8] = {h0.x, h0.y, h0.z, h0.w, h1.x, h1.y, h1.z, h1.w};

    const float* wp = cW + lane * 16;
    float4 w0 = *(const float4*)(wp + 0);
    float4 w1 = *(const float4*)(wp + 4);
    float4 w2 = *(const float4*)(wp + 8);
    float4 w3 = *(const float4*)(wp + 12);
    float wv[16] = {w0.x, w0.y, w0.z, w0.w, w1.x, w1.y, w1.z, w1.w,
                    w2.x, w2.y, w2.z, w2.w, w3.x, w3.y, w3.z, w3.w};

    float c0 = 0.f, c1 = 0.f;
#pragma unroll
    for (int j = 0; j < 8; j++) {
        c0 += hv[j] * wv[2 * j];
        c1 += hv[j] * wv[2 * j + 1];
    }
#pragma unroll
    for (int off = 16; off > 0; off >>= 1) {
        c0 += __shfl_xor_sync(0xffffffffu, c0, off);
        c1 += __shfl_xor_sync(0xffffffffu, c1, off);
    }
    if (lane == 0) {
        outp[(size_t)idx * 2 + 0] = c0 + cb[0];
        outp[(size_t)idx * 2 + 1] = c1 + cb[1];
    }
}

// ---------------- launch ----------------
extern "C" void kernel_launch(void* const* d_in, const int* in_sizes, int n_in,
                              void* d_out, int out_size) {
    const float* x[3];
    const int*   ei[3];
    for (int i = 0; i < 3; i++) {
        x[i]  = (const float*)d_in[i];
        ei[i] = (const int*)d_in[3 + i];
    }
    const float* Wl1  = (const float*)d_in[6];
    const float* Wr1  = (const float*)d_in[7];
    const float* att1 = (const float*)d_in[8];
    const float* b1   = (const float*)d_in[9];
    const float* Wl2  = (const float*)d_in[10];
    const float* Wr2  = (const float*)d_in[11];
    const float* att2 = (const float*)d_in[12];
    const float* b2   = (const float*)d_in[13];
    const float* bng  = (const float*)d_in[14];
    const float* bnb  = (const float*)d_in[15];
    const float* cW   = (const float*)d_in[16];
    const float* cb   = (const float*)d_in[17];
    float* out = (float*)d_out;

    float *hl, *hr, *h, *hn, *bnsum, *bnsq, *scale, *shift;
    __half *Ah, *Bh;
    int *rowptr, *csrsrc, *deg, *cursor, *bsum;
    cudaGetSymbolAddress((void**)&hl,     g_hl);
    cudaGetSymbolAddress((void**)&hr,     g_hr);
    cudaGetSymbolAddress((void**)&h,      g_h);
    cudaGetSymbolAddress((void**)&hn,     g_hn);
    cudaGetSymbolAddress((void**)&Ah,     g_Ah);
    cudaGetSymbolAddress((void**)&Bh,     g_Bh);
    cudaGetSymbolAddress((void**)&rowptr, g_rowptr);
    cudaGetSymbolAddress((void**)&csrsrc, g_csrsrc);
    cudaGetSymbolAddress((void**)&deg,    g_deg);
    cudaGetSymbolAddress((void**)&cursor, g_cursor);
    cudaGetSymbolAddress((void**)&bsum,   g_bsum);
    cudaGetSymbolAddress((void**)&bnsum,  g_bnsum);
    cudaGetSymbolAddress((void**)&bnsq,   g_bnsq);
    cudaGetSymbolAddress((void**)&scale,  g_scale);
    cudaGetSymbolAddress((void**)&shift,  g_shift);

    cudaFuncSetAttribute(gemm_mma_kernel,
                         cudaFuncAttributeMaxDynamicSharedMemorySize, GEMM_SMEM);

    // geometry
    int N0 = in_sizes[0] / 128, N1 = in_sizes[1] / 128, N2 = in_sizes[2] / 128;
    int E0 = in_sizes[3] / 2,   E1 = in_sizes[4] / 2,   E2 = in_sizes[5] / 2;
    int T0 = (N0 + 127) / 128, T1 = (N1 + 127) / 128, T2 = (N2 + 127) / 128;
    int P1 = T0 * 128, P2 = P1 + T1 * 128;
    int NPAD = P2 + T2 * 128;
    int ET = E0 + E1 + E2;
    int ntile = NPAD / 128;
    int nb = (NPAD + 1023) / 1024;

    // --- prep; layer-1 GEMM at launch index 4 so ncu profiles it ---
    split_x_kernel<<<(NPAD * 32 + 255) / 256, 256>>>(x[0], x[1], x[2], Ah,
                                                     P1, P2, N0, N1, N2, NPAD);   // 0
    {
        int tot = 3 * 128 * 512 + 3 * 256 * 512;
        pack_weights_kernel<<<(tot + 255) / 256, 256>>>(Wl1, Wr1, Wl2, Wr2, Bh);  // 1
    }
    cudaMemsetAsync(deg, 0, NPAD * sizeof(int), 0);                               // 2
    hist_kernel<<<(ET + 255) / 256, 256>>>(ei[0] + E0, ei[1] + E1, ei[2] + E2,
                                           deg, E0, E1, E2, P1, P2);              // 3

    dim3 gg(4, ntile);
    gemm_mma_kernel<<<gg, 256, GEMM_SMEM>>>(Ah, Bh, hl, hr,
                                            P1, P2, N0, N1, N2, 128, 0);          // 4 (profiled)

    scan_bsum_kernel<<<nb, 256>>>(deg, bsum, NPAD);
    scan_boff_kernel<<<1, 32>>>(bsum, rowptr, nb, NPAD);
    scan_final_kernel<<<nb, 1024>>>(deg, bsum, rowptr, NPAD);
    cudaMemsetAsync(cursor, 0, NPAD * sizeof(int), 0);
    scatter_kernel<<<(ET + 255) / 256, 256>>>(ei[0], ei[0] + E0, ei[1], ei[1] + E1,
                                              ei[2], ei[2] + E2,
                                              rowptr, cursor, csrsrc, E0, E1, E2, P1, P2);

    for (int layer = 0; layer < 2; layer++) {
        if (layer == 1) {
            gemm_mma_kernel<<<gg, 256, GEMM_SMEM>>>(Ah, Bh, hl, hr,
                                                    P1, P2, N0, N1, N2, 256, L2_WOFF);
        }
        const float* at = (layer == 0) ? att1 : att2;
        const float* bs = (layer == 0) ? b1 : b2;

        gat_kernel<<<(NPAD * 32 + 255) / 256, 256>>>(hl, hr, rowptr, csrsrc, at, bs, h,
                                                     P1, P2, N0, N1, N2, NPAD);

        cudaMemsetAsync(bnsum, 0, 768 * sizeof(float), 0);
        cudaMemsetAsync(bnsq,  0, 768 * sizeof(float), 0);
        {
            dim3 gs(128, 3);
            bn_stats_kernel<<<gs, 256>>>(h, bnsum, bnsq, P1, P2, N0, N1, N2);
        }
        bn_final_kernel<<<3, 256>>>(bnsum, bnsq, bng, bnb, scale, shift, N0, N1, N2);
        bn_apply_kernel<<<(NPAD * 64 + 255) / 256, 256>>>(
            h, hn, Ah, scale, shift, P1, P2, NPAD,
            layer == 0 ? 1 : 0, layer == 0 ? 0 : 1);
    }

    classifier_kernel<<<((N0 + N1 + N2) * 32 + 255) / 256, 256>>>(
        hn, cW, cb, out, P1, P2, N0, N1, N2);
}